// round 2
// baseline (speedup 1.0000x reference)
#include <cuda_runtime.h>
#include <cuda_bf16.h>

// Problem constants
#define BB 16384
#define SS 4
#define LL 16
#define DD 256
#define BOS_ID 98

// One thread per float4 of output. Output shape (B, S+1, D) fp32.
// Row = 256 floats = 64 float4 -> 64 threads per row (2 warps, branch-uniform).
__global__ void __launch_bounds__(256) actions_emb_kernel(
    const int*    __restrict__ char_ids,     // (B, S, L)
    const int*    __restrict__ char_len,     // (B, S)
    const int*    __restrict__ action_ids,   // (B, S)
    const int*    __restrict__ slot_type,    // (B, S)
    const float4* __restrict__ char_table,   // (N_CHAR, D/4)
    const float4* __restrict__ action_table, // (N_ACT, D/4)
    float4*       __restrict__ out)          // (B, S+1, D/4)
{
    const int v   = blockIdx.x * blockDim.x + threadIdx.x;   // float4 index
    const int d4  = v & 63;          // 0..63 within row
    const int row = v >> 6;          // (b * 5 + s)
    const int s   = row % 5;
    const int b   = row / 5;
    if (b >= BB) return;

    float4 r;
    if (s == 0) {
        // BOS row: broadcast action_table[BOS_ID] (L1-resident after warmup)
        r = __ldg(&action_table[BOS_ID * (DD / 4) + d4]);
    } else {
        const int bs = b * SS + (s - 1);
        const int t  = __ldg(&slot_type[bs]);
        if (t == 0) {
            const int len = __ldg(&char_len[bs]);          // 1..15
            const int* ids = char_ids + bs * LL;
            // Two independent accumulator chains -> 2x MLP on L1-hit gathers.
            float ax = 0.f, ay = 0.f, az = 0.f, aw = 0.f;
            float bx = 0.f, by = 0.f, bz = 0.f, bw = 0.f;
            int l = 0;
            for (; l + 1 < len; l += 2) {
                const int id0 = __ldg(&ids[l]);            // warp-uniform broadcast
                const int id1 = __ldg(&ids[l + 1]);
                const float4 e0 = __ldg(&char_table[id0 * (DD / 4) + d4]);
                const float4 e1 = __ldg(&char_table[id1 * (DD / 4) + d4]);
                ax += e0.x; ay += e0.y; az += e0.z; aw += e0.w;
                bx += e1.x; by += e1.y; bz += e1.z; bw += e1.w;
            }
            if (l < len) {
                const int id0 = __ldg(&ids[l]);
                const float4 e0 = __ldg(&char_table[id0 * (DD / 4) + d4]);
                ax += e0.x; ay += e0.y; az += e0.z; aw += e0.w;
            }
            const float inv = 1.0f / (float)len;
            r.x = (ax + bx) * inv;
            r.y = (ay + by) * inv;
            r.z = (az + bz) * inv;
            r.w = (aw + bw) * inv;
        } else if (t == 1) {
            const int a = __ldg(&action_ids[bs]);
            r = __ldg(&action_table[a * (DD / 4) + d4]);
        } else {
            r.x = 0.f; r.y = 0.f; r.z = 0.f; r.w = 0.f;
        }
    }
    out[v] = r;
}

extern "C" void kernel_launch(void* const* d_in, const int* in_sizes, int n_in,
                              void* d_out, int out_size)
{
    const int*    char_ids     = (const int*)   d_in[0];
    const int*    char_len     = (const int*)   d_in[1];
    const int*    action_ids   = (const int*)   d_in[2];
    const int*    slot_type    = (const int*)   d_in[3];
    const float4* char_table   = (const float4*)d_in[4];
    const float4* action_table = (const float4*)d_in[5];
    float4*       out          = (float4*)      d_out;

    const long long total_vec4 = (long long)BB * 5 * (DD / 4);  // 5,242,880
    const int threads = 256;
    const int blocks  = (int)((total_vec4 + threads - 1) / threads);

    actions_emb_kernel<<<blocks, threads>>>(char_ids, char_len, action_ids,
                                            slot_type, char_table, action_table, out);
}

// round 3
// speedup vs baseline: 1.4557x; 1.4557x over previous
#include <cuda_runtime.h>
#include <cuda_bf16.h>

#define BB 16384
#define SS 4
#define LL 16
#define DD 256
#define BOS_ID 98
#define D4 (DD / 4)   // 64 float4 per row

// One warp per output row (b, s) of the (B, 5, 256) fp32 output.
// Each thread produces 2 float4: columns lane and lane+32.
// All control data (slot_type, char_len, char_ids) is warp-uniform.
__global__ void __launch_bounds__(256) actions_emb_kernel(
    const int*    __restrict__ char_ids,     // (B, S, L)
    const int*    __restrict__ char_len,     // (B, S)
    const int*    __restrict__ action_ids,   // (B, S)
    const int*    __restrict__ slot_type,    // (B, S)
    const float4* __restrict__ char_table,   // (N_CHAR, 64)
    const float4* __restrict__ action_table, // (N_ACT, 64)
    float4*       __restrict__ out)          // (B, 5, 64)
{
    const int gtid = blockIdx.x * blockDim.x + threadIdx.x;
    const int row  = gtid >> 5;              // warp id == output row (b*5 + s)
    const int lane = gtid & 31;
    if (row >= BB * 5) return;

    const int s = row % 5;
    const int b = row / 5;

    float4 r0, r1;

    if (s == 0) {
        r0 = __ldg(&action_table[BOS_ID * D4 + lane]);
        r1 = __ldg(&action_table[BOS_ID * D4 + 32 + lane]);
    } else {
        const int bs = b * SS + (s - 1);
        const int t  = __ldg(&slot_type[bs]);            // warp-uniform
        if (t == 0) {
            const int len = __ldg(&char_len[bs]);        // 1..15, warp-uniform
            const int4* ids4 = (const int4*)(char_ids + bs * LL);
            float4 a0 = make_float4(0.f, 0.f, 0.f, 0.f);
            float4 a1 = make_float4(0.f, 0.f, 0.f, 0.f);
            const int nb = (len + 3) >> 2;               // 1..4 batches
            for (int i = 0; i < nb; ++i) {
                const int4 id = __ldg(&ids4[i]);         // 4 ids, one uniform LDG.128
                const int base = i << 2;
                // 8 independent L1-hit loads in flight before any use.
                const float4 ex0 = __ldg(&char_table[id.x * D4 + lane]);
                const float4 ex1 = __ldg(&char_table[id.x * D4 + 32 + lane]);
                const float4 ey0 = __ldg(&char_table[id.y * D4 + lane]);
                const float4 ey1 = __ldg(&char_table[id.y * D4 + 32 + lane]);
                const float4 ez0 = __ldg(&char_table[id.z * D4 + lane]);
                const float4 ez1 = __ldg(&char_table[id.z * D4 + 32 + lane]);
                const float4 ew0 = __ldg(&char_table[id.w * D4 + lane]);
                const float4 ew1 = __ldg(&char_table[id.w * D4 + 32 + lane]);
                // Branchless masking: ids beyond len are valid table indices,
                // just weighted 0. Keeps loads unconditional and batched.
                const float mx = 1.0f;                            // base+0 < len always (i < nb)
                const float my = (base + 1 < len) ? 1.0f : 0.0f;
                const float mz = (base + 2 < len) ? 1.0f : 0.0f;
                const float mw = (base + 3 < len) ? 1.0f : 0.0f;
                a0.x = fmaf(mx, ex0.x, a0.x); a0.y = fmaf(mx, ex0.y, a0.y);
                a0.z = fmaf(mx, ex0.z, a0.z); a0.w = fmaf(mx, ex0.w, a0.w);
                a1.x = fmaf(mx, ex1.x, a1.x); a1.y = fmaf(mx, ex1.y, a1.y);
                a1.z = fmaf(mx, ex1.z, a1.z); a1.w = fmaf(mx, ex1.w, a1.w);
                a0.x = fmaf(my, ey0.x, a0.x); a0.y = fmaf(my, ey0.y, a0.y);
                a0.z = fmaf(my, ey0.z, a0.z); a0.w = fmaf(my, ey0.w, a0.w);
                a1.x = fmaf(my, ey1.x, a1.x); a1.y = fmaf(my, ey1.y, a1.y);
                a1.z = fmaf(my, ey1.z, a1.z); a1.w = fmaf(my, ey1.w, a1.w);
                a0.x = fmaf(mz, ez0.x, a0.x); a0.y = fmaf(mz, ez0.y, a0.y);
                a0.z = fmaf(mz, ez0.z, a0.z); a0.w = fmaf(mz, ez0.w, a0.w);
                a1.x = fmaf(mz, ez1.x, a1.x); a1.y = fmaf(mz, ez1.y, a1.y);
                a1.z = fmaf(mz, ez1.z, a1.z); a1.w = fmaf(mz, ez1.w, a1.w);
                a0.x = fmaf(mw, ew0.x, a0.x); a0.y = fmaf(mw, ew0.y, a0.y);
                a0.z = fmaf(mw, ew0.z, a0.z); a0.w = fmaf(mw, ew0.w, a0.w);
                a1.x = fmaf(mw, ew1.x, a1.x); a1.y = fmaf(mw, ew1.y, a1.y);
                a1.z = fmaf(mw, ew1.z, a1.z); a1.w = fmaf(mw, ew1.w, a1.w);
            }
            const float inv = 1.0f / (float)len;
            r0.x = a0.x * inv; r0.y = a0.y * inv; r0.z = a0.z * inv; r0.w = a0.w * inv;
            r1.x = a1.x * inv; r1.y = a1.y * inv; r1.z = a1.z * inv; r1.w = a1.w * inv;
        } else if (t == 1) {
            const int a = __ldg(&action_ids[bs]);
            r0 = __ldg(&action_table[a * D4 + lane]);
            r1 = __ldg(&action_table[a * D4 + 32 + lane]);
        } else {
            r0 = make_float4(0.f, 0.f, 0.f, 0.f);
            r1 = make_float4(0.f, 0.f, 0.f, 0.f);
        }
    }

    float4* orow = out + (long long)row * D4;
    orow[lane]      = r0;
    orow[lane + 32] = r1;
}

extern "C" void kernel_launch(void* const* d_in, const int* in_sizes, int n_in,
                              void* d_out, int out_size)
{
    const int*    char_ids     = (const int*)   d_in[0];
    const int*    char_len     = (const int*)   d_in[1];
    const int*    action_ids   = (const int*)   d_in[2];
    const int*    slot_type    = (const int*)   d_in[3];
    const float4* char_table   = (const float4*)d_in[4];
    const float4* action_table = (const float4*)d_in[5];
    float4*       out          = (float4*)      d_out;

    const int rows    = BB * 5;                 // 81920 warps
    const int threads = 256;                    // 8 warps per block
    const int blocks  = (rows * 32) / threads;  // 10240

    actions_emb_kernel<<<blocks, threads>>>(char_ids, char_len, action_ids,
                                            slot_type, char_table, action_table, out);
}